// round 1
// baseline (speedup 1.0000x reference)
#include <cuda_runtime.h>
#include <cuda_bf16.h>

// HorizontalDilation: out[r][c] = max(0, max_{d=-7..7} in[r][clamp-or-zero(c+d)])
// Window k=15, zero padding; zero-padding + final relu => OOB can be treated as 0.0f.
//
// Strategy: one block per row (4096 blocks x 256 threads), 16 outputs/thread.
// Each thread loads 32 floats [b-8, b+24) via 8 aligned float4 loads, then does
// an in-place log-doubling sliding max (windows 2 -> 4 -> 8 -> 15) entirely in
// registers. Relu is folded into the final stage. 4 float4 stores.

#define IMG_W 4096
#define IMG_H 4096
#define PER_THREAD 16
#define THREADS 256

__global__ __launch_bounds__(THREADS)
void HorizontalDilation_kernel(const float* __restrict__ in, float* __restrict__ out) {
    const int row = blockIdx.x;
    const int b = threadIdx.x * PER_THREAD;          // first output column of this thread
    const float* __restrict__ r = in + (size_t)row * IMG_W;

    float x[32];

    if (b >= 8 && b + 24 <= IMG_W) {
        // Fast path: fully interior, aligned float4 loads of [b-8, b+24)
        const float4* __restrict__ p = (const float4*)(r + b - 8);
        #pragma unroll
        for (int i = 0; i < 8; i++) {
            float4 v = p[i];
            x[4 * i + 0] = v.x;
            x[4 * i + 1] = v.y;
            x[4 * i + 2] = v.z;
            x[4 * i + 3] = v.w;
        }
    } else {
        // Edge threads (tid 0 and 255 only): scalar bounds-checked loads, OOB -> 0
        #pragma unroll
        for (int i = 0; i < 32; i++) {
            int c = b - 8 + i;
            x[i] = (c >= 0 && c < IMG_W) ? r[c] : 0.0f;
        }
    }

    // In-place log-doubling sliding max. Ascending order is safe: step i reads
    // x[i+s] which has not been overwritten yet (it is overwritten at step i+s).
    // After stage s, x[i] = max(orig x[i .. i+s_width-1]).
    #pragma unroll
    for (int i = 1; i < 30; i++) x[i] = fmaxf(x[i], x[i + 1]);   // width 2, valid 1..29
    #pragma unroll
    for (int i = 1; i < 28; i++) x[i] = fmaxf(x[i], x[i + 2]);   // width 4, valid 1..27
    #pragma unroll
    for (int i = 1; i < 24; i++) x[i] = fmaxf(x[i], x[i + 4]);   // width 8, valid 1..23
    #pragma unroll
    for (int i = 1; i < 17; i++)                                  // width 15 + relu
        x[i] = fmaxf(fmaxf(x[i], x[i + 7]), 0.0f);

    // Output j (j=0..15) = x[j+1], covering columns b+j-7 .. b+j+7.
    float* __restrict__ o = out + (size_t)row * IMG_W + b;
    #pragma unroll
    for (int i = 0; i < 4; i++) {
        float4 v = make_float4(x[1 + 4 * i], x[2 + 4 * i], x[3 + 4 * i], x[4 + 4 * i]);
        ((float4*)o)[i] = v;
    }
}

extern "C" void kernel_launch(void* const* d_in, const int* in_sizes, int n_in,
                              void* d_out, int out_size) {
    const float* img = (const float*)d_in[0];
    float* out = (float*)d_out;
    (void)in_sizes; (void)n_in; (void)out_size;

    dim3 grid(IMG_H);          // one block per row
    dim3 block(THREADS);       // 256 threads * 16 outputs = 4096 cols
    HorizontalDilation_kernel<<<grid, block>>>(img, out);
}

// round 2
// speedup vs baseline: 1.2740x; 1.2740x over previous
#include <cuda_runtime.h>
#include <cuda_bf16.h>

// HorizontalDilation: out[r][c] = max(0, max_{d=-7..7} in[r][c+d]), zero padding.
// Window k=15. Zero padding + final relu => OOB can be treated as exactly 0.0f.
//
// Round-2 design: lane-interleaved warp kernel.
//  - Each lane owns ONE 4-column group: lane l of a warp-chunk loads float4 at
//    col0 = C - 8 + 4*l. Adjacent lanes are 16B apart -> every LDG.128/STG.128
//    is 512B lane-contiguous = 4 L1 wavefronts (vs 16 in round 1).
//  - The 15-wide window around a lane's group spans groups l-2..l+2 only.
//    Lane precomputes group suffix maxes (suf1..3), prefix maxes (pre1..3) and
//    m4, then grabs neighbor aggregates with 8 warp shuffles (no memory).
//  - Edge lanes 0,1,30,31 lack valid shuffle sources, so a warp outputs only
//    its middle 112 columns (lanes 2..29). 37 chunks of 112 cover a 4096 row.

#define IMG_W 4096
#define IMG_H 4096
#define OUT_PER_WARP 112
#define CHUNKS 37              // ceil(4096 / 112)
#define THREADS 128            // 4 warps / block

__global__ __launch_bounds__(THREADS)
void HorizontalDilation_kernel(const float* __restrict__ in, float* __restrict__ out) {
    const unsigned FULL = 0xffffffffu;
    const int wid  = (blockIdx.x * THREADS + threadIdx.x) >> 5;   // global warp id
    const int lane = threadIdx.x & 31;
    const int row  = wid / CHUNKS;
    const int chunk = wid - row * CHUNKS;
    const int C = chunk * OUT_PER_WARP;          // first output col of this chunk
    const int col0 = C - 8 + 4 * lane;           // lane's group: cols col0..col0+3

    const float* __restrict__ r = in + (size_t)row * IMG_W;

    // Load own group (col0 is a multiple of 4 -> float4 aligned). OOB groups are
    // always fully OOB (4096 % 4 == 0), substitute 0.0f (exact per relu semantics).
    float4 v;
    if (col0 >= 0 && col0 < IMG_W) {
        v = *(const float4*)(r + col0);
    } else {
        v = make_float4(0.f, 0.f, 0.f, 0.f);
    }

    // Group aggregates: suffix maxes, prefix maxes, full max.
    const float suf1 = v.w;
    const float suf2 = fmaxf(v.z, suf1);
    const float suf3 = fmaxf(v.y, suf2);
    const float m4   = fmaxf(v.x, suf3);
    const float pre1 = v.x;
    const float pre2 = fmaxf(pre1, v.y);
    const float pre3 = fmaxf(pre2, v.z);

    // Neighbor aggregates via shuffles (valid for lanes 2..29, the producers).
    const float m4_m1 = __shfl_up_sync  (FULL, m4,   1);  // group l-1
    const float m4_p1 = __shfl_down_sync(FULL, m4,   1);  // group l+1
    const float s1    = __shfl_up_sync  (FULL, suf1, 2);  // group l-2
    const float s2    = __shfl_up_sync  (FULL, suf2, 2);
    const float s3    = __shfl_up_sync  (FULL, suf3, 2);
    const float p1    = __shfl_down_sync(FULL, pre1, 2);  // group l+2
    const float p2    = __shfl_down_sync(FULL, pre2, 2);
    const float p3    = __shfl_down_sync(FULL, pre3, 2);

    // Windows for outputs at cols col0+j (j=0..3):
    //  j=0: [col0-7, col0+7]  = suf3[l-2] | m4[l-1] | m4[l] | m4[l+1]
    //  j=1: [col0-6, col0+8]  = suf2[l-2] | core | pre1[l+2]
    //  j=2: [col0-5, col0+9]  = suf1[l-2] | core | pre2[l+2]
    //  j=3: [col0-4, col0+10] =            m4[l-1..l+1]     | pre3[l+2]
    const float core = fmaxf(fmaxf(m4_m1, m4), m4_p1);
    float4 o;
    o.x = fmaxf(fmaxf(core, s3), 0.f);
    o.y = fmaxf(fmaxf(fmaxf(core, s2), p1), 0.f);
    o.z = fmaxf(fmaxf(fmaxf(core, s1), p2), 0.f);
    o.w = fmaxf(fmaxf(core, p3), 0.f);

    // Lane l's output group is the same columns it loaded (col0..col0+3).
    if (lane >= 2 && lane <= 29 && col0 < IMG_W) {
        *(float4*)(out + (size_t)row * IMG_W + col0) = o;
    }
}

extern "C" void kernel_launch(void* const* d_in, const int* in_sizes, int n_in,
                              void* d_out, int out_size) {
    const float* img = (const float*)d_in[0];
    float* outp = (float*)d_out;
    (void)in_sizes; (void)n_in; (void)out_size;

    // Total warps = IMG_H * CHUNKS = 4096 * 37 = 151552; 4 warps per block.
    const int total_warps = IMG_H * CHUNKS;
    const int blocks = total_warps / (THREADS / 32);   // 37888
    HorizontalDilation_kernel<<<blocks, THREADS>>>(img, outp);
}

// round 3
// speedup vs baseline: 1.3482x; 1.0582x over previous
#include <cuda_runtime.h>
#include <cuda_bf16.h>

// HorizontalDilation: out[r][c] = max(0, max_{d=-7..7} in[r][c+d]), zero padding.
// Window k=15. Zero padding + final relu => OOB values can be treated as 0.0f.
//
// Round-3 design: 8 columns per lane, warp-shuffle aggregates, MLP=2.
//  - Lane l of a chunk owns cols col0..col0+7, col0 = C - 8 + 8*l.
//    Two aligned float4 loads (independent -> 2 outstanding LDGs per thread).
//  - +/-7 window spans only lanes l-1, l, l+1. Lane computes prefix maxes
//    pre1..7, suffix maxes suf1..7, full max m8; neighbors fetched with 14
//    warp shuffles. out[j] = max(suf_{7-j}[l-1], m8, pre_j[l+1], 0).
//  - Lanes 1..30 store => 240 outputs per 256 loaded cols (6.7% halo overlap).
//  - 18 chunks of 240 cover a 4096 row; grid = (3 blocks x 6 warps, 4096 rows).
//    No integer division anywhere.

#define IMG_W 4096
#define IMG_H 4096
#define OUT_PER_WARP 240
#define WARPS_PER_BLOCK 6
#define THREADS (WARPS_PER_BLOCK * 32)   // 192

__global__ __launch_bounds__(THREADS)
void HorizontalDilation_kernel(const float* __restrict__ in, float* __restrict__ out) {
    const unsigned FULL = 0xffffffffu;
    const int lane = threadIdx.x & 31;
    const int warp = threadIdx.x >> 5;
    const int row  = blockIdx.y;
    const int chunk = blockIdx.x * WARPS_PER_BLOCK + warp;      // 0..17
    const int C = chunk * OUT_PER_WARP;                         // first output col
    const int col0 = C - 8 + 8 * lane;                          // lane's 8-col group

    const float* __restrict__ r = in + (size_t)row * IMG_W;

    // Groups are 8-aligned and IMG_W % 8 == 0 -> each group fully in or out.
    const bool inb = (col0 >= 0) & (col0 < IMG_W);

    // Issue both loads before any compute (MLP = 2).
    float4 a = make_float4(0.f, 0.f, 0.f, 0.f);
    float4 b = make_float4(0.f, 0.f, 0.f, 0.f);
    if (inb) {
        a = *(const float4*)(r + col0);
        b = *(const float4*)(r + col0 + 4);
    }

    // v0..v7 = a.x a.y a.z a.w b.x b.y b.z b.w
    // Suffix maxes: suf_i = max of last i elements. Prefix: pre_i = max of first i.
    const float suf1 = b.w;
    const float suf2 = fmaxf(b.z, suf1);
    const float suf3 = fmaxf(b.y, suf2);
    const float suf4 = fmaxf(b.x, suf3);
    const float suf5 = fmaxf(a.w, suf4);
    const float suf6 = fmaxf(a.z, suf5);
    const float suf7 = fmaxf(a.y, suf6);
    const float m8   = fmaxf(a.x, suf7);
    const float pre1 = a.x;
    const float pre2 = fmaxf(pre1, a.y);
    const float pre3 = fmaxf(pre2, a.z);
    const float pre4 = fmaxf(pre3, a.w);
    const float pre5 = fmaxf(pre4, b.x);
    const float pre6 = fmaxf(pre5, b.y);
    const float pre7 = fmaxf(pre6, b.z);

    // Neighbor aggregates.
    const float sU1 = __shfl_up_sync(FULL, suf1, 1);
    const float sU2 = __shfl_up_sync(FULL, suf2, 1);
    const float sU3 = __shfl_up_sync(FULL, suf3, 1);
    const float sU4 = __shfl_up_sync(FULL, suf4, 1);
    const float sU5 = __shfl_up_sync(FULL, suf5, 1);
    const float sU6 = __shfl_up_sync(FULL, suf6, 1);
    const float sU7 = __shfl_up_sync(FULL, suf7, 1);
    const float pD1 = __shfl_down_sync(FULL, pre1, 1);
    const float pD2 = __shfl_down_sync(FULL, pre2, 1);
    const float pD3 = __shfl_down_sync(FULL, pre3, 1);
    const float pD4 = __shfl_down_sync(FULL, pre4, 1);
    const float pD5 = __shfl_down_sync(FULL, pre5, 1);
    const float pD6 = __shfl_down_sync(FULL, pre6, 1);
    const float pD7 = __shfl_down_sync(FULL, pre7, 1);

    // out[j] (col col0+j), window [col0+j-7, col0+j+7]:
    //   j=0: suf7[l-1] | m8            j=7: m8 | pre7[l+1]
    //   else: suf_{7-j}[l-1] | m8 | pre_j[l+1]
    const float m8r = fmaxf(m8, 0.f);
    float4 oa, ob;
    oa.x = fmaxf(m8r, sU7);
    oa.y = fmaxf(fmaxf(m8r, sU6), pD1);
    oa.z = fmaxf(fmaxf(m8r, sU5), pD2);
    oa.w = fmaxf(fmaxf(m8r, sU4), pD3);
    ob.x = fmaxf(fmaxf(m8r, sU3), pD4);
    ob.y = fmaxf(fmaxf(m8r, sU2), pD5);
    ob.z = fmaxf(fmaxf(m8r, sU1), pD6);
    ob.w = fmaxf(m8r, pD7);

    // Lanes 1..30 store their own 8 columns (write-once -> streaming stores).
    if (lane >= 1 && lane <= 30 && inb) {
        float* o = out + (size_t)row * IMG_W + col0;
        __stcs((float4*)o, oa);
        __stcs((float4*)(o + 4), ob);
    }
}

extern "C" void kernel_launch(void* const* d_in, const int* in_sizes, int n_in,
                              void* d_out, int out_size) {
    const float* img = (const float*)d_in[0];
    float* outp = (float*)d_out;
    (void)in_sizes; (void)n_in; (void)out_size;

    // 18 chunks/row = 3 blocks x 6 warps; 4096 rows.
    dim3 grid(3, IMG_H);
    dim3 block(THREADS);
    HorizontalDilation_kernel<<<grid, block>>>(img, outp);
}